// round 16
// baseline (speedup 1.0000x reference)
#include <cuda_runtime.h>
#include <cuda_bf16.h>

// DWTLoss: single-level Haar DWT L1 loss between pred and target.
// [32,3,512,512] fp32 x2 = 201.3 MB streamed once -> HBM-bound.
//
// Per 2x2 block with diffs da,db,dc,dd:
//   sum of 4 normalized subband |.| terms = max(|da+db|,|dc+dd|) + max(|da-db|,|dc-dd|)
// loss = (1/N_BLOCKS) * sum, N_BLOCKS = 32*3*256*256.
//
// R14: convergence on the best-profiled structure. R7's plain grid-stride
// (best measured: 33.15us kernel, DRAM 78.4%) + dual accumulators. The
// two-phase remainder variants (R8-R12) profiled 0.7-1.0us slower; bench
// differences across all of them are within +-1us noise. 1184 = 148*8 CTAs
// x 256 thr, __launch_bounds__(256,8) -> <=32 regs, one full wave,
// 10-11 items/thread.

#define N_BLOCKS_HAAR (32 * 3 * 256 * 256)   // 6,291,456
#define N_ITEMS       (32 * 3 * 256 * 128)   // 3,145,728 float4-pair items
#define GRID_CTAS     1184                    // 148 * 8 -> exactly one full wave
#define CTA_THREADS   256
#define N_THREADS     (GRID_CTAS * CTA_THREADS)   // 303,104
#define ROW_F4        128                          // float4 per 512-wide row

__device__ double g_dwt_acc;
__device__ unsigned int g_dwt_count;

__global__ void __launch_bounds__(CTA_THREADS, 8) dwt_loss_fused_kernel(
    const float* __restrict__ pred,
    const float* __restrict__ target,
    float* __restrict__ out)
{
    const float4* __restrict__ p4 = (const float4*)pred;
    const float4* __restrict__ t4 = (const float4*)target;

    const int tid = blockIdx.x * CTA_THREADS + threadIdx.x;

    float acc0 = 0.0f, acc1 = 0.0f;
    #pragma unroll 2
    for (int i = tid; i < N_ITEMS; i += N_THREADS) {
        // item i = (plane, row-pair, col4); float4 index of top row:
        //   base = i + (i & ~127)   (absorbs plane*2 and row-pair*2 doubling)
        const int base = i + (i & ~127);

        float4 p0 = p4[base];
        float4 p1 = p4[base + ROW_F4];
        float4 q0 = t4[base];
        float4 q1 = t4[base + ROW_F4];

        // block 0 (lanes x,y) -> acc0 chain
        float da = p0.x - q0.x, db = p0.y - q0.y;
        float dc = p1.x - q1.x, dd = p1.y - q1.y;
        acc0 += fmaxf(fabsf(da + db), fabsf(dc + dd))
              + fmaxf(fabsf(da - db), fabsf(dc - dd));

        // block 1 (lanes z,w) -> acc1 chain (independent)
        da = p0.z - q0.z; db = p0.w - q0.w;
        dc = p1.z - q1.z; dd = p1.w - q1.w;
        acc1 += fmaxf(fabsf(da + db), fabsf(dc + dd))
              + fmaxf(fabsf(da - db), fabsf(dc - dd));
    }

    float acc = acc0 + acc1;

    // intra-warp reduce
    #pragma unroll
    for (int o = 16; o > 0; o >>= 1)
        acc += __shfl_xor_sync(0xffffffffu, acc, o);

    __shared__ float sm[CTA_THREADS / 32];
    const int lane = threadIdx.x & 31;
    const int warp = threadIdx.x >> 5;
    if (lane == 0) sm[warp] = acc;
    __syncthreads();

    if (warp == 0) {
        float v = (lane < CTA_THREADS / 32) ? sm[lane] : 0.0f;
        #pragma unroll
        for (int o = 4; o > 0; o >>= 1)
            v += __shfl_xor_sync(0xffffffffu, v, o);

        if (lane == 0) {
            atomicAdd(&g_dwt_acc, (double)v);
            __threadfence();
            unsigned int prev = atomicAdd(&g_dwt_count, 1u);
            if (prev == GRID_CTAS - 1) {
                // last CTA: all g_dwt_acc adds visible (fence + atomic order).
                // Read-and-reset so every graph replay starts from zeroed state.
                unsigned long long raw =
                    atomicExch((unsigned long long*)&g_dwt_acc, 0ull);
                double total = __longlong_as_double((long long)raw);
                out[0] = (float)(total * (1.0 / (double)N_BLOCKS_HAAR));
                atomicExch(&g_dwt_count, 0u);
            }
        }
    }
}

extern "C" void kernel_launch(void* const* d_in, const int* in_sizes, int n_in,
                              void* d_out, int out_size) {
    const float* pred   = (const float*)d_in[0];
    const float* target = (const float*)d_in[1];
    float* out = (float*)d_out;

    dwt_loss_fused_kernel<<<GRID_CTAS, CTA_THREADS>>>(pred, target, out);
}